// round 1
// baseline (speedup 1.0000x reference)
#include <cuda_runtime.h>
#include <cstdint>

#define B_ 2
#define T_ 2048
#define D_ 1024
#define NH 16
#define DH 64
#define AMAX 15
#define NT (B_*T_)          // 4096 tokens
#define NEGF (-1e30f)

// ---------------- scratch (no allocs allowed -> __device__ globals) ----------
__device__ float g_integral[NT * D_];          // 16 MB
__device__ float g_deriv[NT * D_];             // 16 MB
__device__ float g_P[NT * 3 * D_];             // 48 MB  x @ Wp^T (all 3 proj)
__device__ float g_I[NT * 3 * D_];             // 48 MB  integral @ Wi^T
__device__ float g_Dm[NT * 3 * D_];            // 48 MB  deriv_base @ Wd^T
__device__ float g_q[NT * D_];
__device__ float g_k[NT * D_];
__device__ float g_v[NT * D_];
__device__ float g_attn[NT * D_];
__device__ float g_gates[NT * 9];              // final gates g[p][3] per token
__device__ float g_kick[NT * 3];               // stag * kick_strength per proj
__device__ float g_wkick[3 * D_];              // Wd[p] @ kick_v[p]

// ---------------- 1) EMA scan + finite difference ---------------------------
// integral[0]=x[0]; integral[t]=0.95*I[t-1]+0.05*x[t];  deriv[t]=x[t]-x[t-1]
__global__ void k_scan(const float* __restrict__ x) {
    int d = blockIdx.x * blockDim.x + threadIdx.x;   // channel 0..1023
    int b = blockIdx.y;
    const float* xb = x + (size_t)b * T_ * D_ + d;
    float* ib = g_integral + (size_t)b * T_ * D_ + d;
    float* db = g_deriv + (size_t)b * T_ * D_ + d;
    float prev = xb[0];
    ib[0] = prev;
    db[0] = 0.f;
    float carry = prev;
    #pragma unroll 4
    for (int t = 1; t < T_; t++) {
        float xv = xb[(size_t)t * D_];
        carry = 0.95f * carry + 0.05f * xv;
        ib[(size_t)t * D_] = carry;
        db[(size_t)t * D_] = xv - prev;
        prev = xv;
    }
}

// ---------------- 2) per-token stats: gates, kick, stagnation ---------------
// 15 reductions of length 1024 per token:
// [0]=|x_t|^2 [1]=|x_{t-1}|^2 [2]=<x_t,x_{t-1}> [3..11]=gate logits [12..14]=kick logits
__global__ void k_stats(const float* __restrict__ x,
                        const float* __restrict__ gate_w,
                        const float* __restrict__ gate_b,
                        const float* __restrict__ kick_w,
                        const float* __restrict__ kick_b) {
    int n = blockIdx.x;
    int t = n % T_;
    int tid = threadIdx.x;                 // 256 threads
    const float* xr = x + (size_t)n * D_;
    const float* xp = xr - D_;             // valid only when t>0

    float s[15];
    #pragma unroll
    for (int i = 0; i < 15; i++) s[i] = 0.f;

    for (int d = tid; d < D_; d += 256) {
        float xv = xr[d];
        float pv = (t > 0) ? xp[d] : 0.f;
        s[0] += xv * xv;
        s[1] += pv * pv;
        s[2] += xv * pv;
        #pragma unroll
        for (int j = 0; j < 9; j++) s[3 + j] += xv * gate_w[j * D_ + d];
        #pragma unroll
        for (int p = 0; p < 3; p++) s[12 + p] += xv * kick_w[p * D_ + d];
    }
    #pragma unroll
    for (int i = 0; i < 15; i++)
        for (int off = 16; off; off >>= 1) s[i] += __shfl_xor_sync(~0u, s[i], off);

    __shared__ float red[8][15];
    int w = tid >> 5, l = tid & 31;
    if (l == 0) {
        #pragma unroll
        for (int i = 0; i < 15; i++) red[w][i] = s[i];
    }
    __syncthreads();
    if (tid == 0) {
        float f[15];
        #pragma unroll
        for (int i = 0; i < 15; i++) {
            float a = 0.f;
            #pragma unroll
            for (int w2 = 0; w2 < 8; w2++) a += red[w2][i];
            f[i] = a;
        }
        float n1 = fmaxf(sqrtf(f[0]), 1e-12f);
        float n2 = fmaxf(sqrtf(f[1]), 1e-12f);
        float cosv = (t > 0) ? f[2] / (n1 * n2) : 0.f;
        float stag = (cosv > 0.95f) ? 1.f : 0.f;
        #pragma unroll
        for (int p = 0; p < 3; p++) {
            float l0 = f[3 + p * 3 + 0] + gate_b[p * 3 + 0];
            float l1 = f[3 + p * 3 + 1] + gate_b[p * 3 + 1];
            float l2 = f[3 + p * 3 + 2] + gate_b[p * 3 + 2];
            float m = fmaxf(l0, fmaxf(l1, l2));
            float e0 = expf(l0 - m), e1 = expf(l1 - m), e2 = expf(l2 - m);
            float inv = 1.f / (e0 + e1 + e2);
            float g0 = fminf(e0 * inv, 0.6f);
            float g1 = fmaxf(fminf(e1 * inv, 0.6f), 0.25f);
            float g2 = fminf(e2 * inv, 0.6f);
            float inv2 = 1.f / (g0 + g1 + g2);
            g_gates[n * 9 + p * 3 + 0] = g0 * inv2;
            g_gates[n * 9 + p * 3 + 1] = g1 * inv2;
            g_gates[n * 9 + p * 3 + 2] = g2 * inv2;
            float ks = 1.f / (1.f + expf(-(f[12 + p] + kick_b[p])));
            g_kick[n * 3 + p] = stag * ks;
        }
    }
}

// ---------------- 3) rank-1 kick precompute: wkick[p] = Wd[p] @ kick_v[p] ---
__global__ void k_wkick(const float* __restrict__ Wd,
                        const float* __restrict__ kick_v) {
    int gw = (blockIdx.x * blockDim.x + threadIdx.x) >> 5;  // warp per output
    int lane = threadIdx.x & 31;
    if (gw >= 3 * D_) return;
    int p = gw / D_, o = gw % D_;
    const float* wr = Wd + (size_t)(p * D_ + o) * D_;
    const float* kv = kick_v + p * D_;
    float s = 0.f;
    for (int d = lane; d < D_; d += 32) s += wr[d] * kv[d];
    for (int off = 16; off; off >>= 1) s += __shfl_xor_sync(~0u, s, off);
    if (lane == 0) g_wkick[p * D_ + o] = s;
}

// ---------------- 4) fp32 SGEMM: C[N,M] = A[N,K] * B[M,K]^T ----------------
// 128x128 tile, BK=16, 256 threads, 8x8 per thread, double-buffered smem.
__device__ __forceinline__ void gemm_nt_dev(const float* __restrict__ A,
                                            const float* __restrict__ Bw,
                                            float* __restrict__ C,
                                            int N, int M, int K) {
    constexpr int BM = 128, BN = 128, BK = 16;
    __shared__ float As[2][BK][BM];
    __shared__ float Bs[2][BK][BN];
    int tid = threadIdx.x;
    int tx = tid & 15, ty = tid >> 4;
    int n0 = blockIdx.y * BM;
    int m0 = blockIdx.x * BN;
    int lr = tid >> 2;            // 0..63
    int lc = (tid & 3) << 2;      // 0,4,8,12

    const float* Ap0 = A + (size_t)(n0 + lr) * K + lc;
    const float* Ap1 = A + (size_t)(n0 + lr + 64) * K + lc;
    const float* Bp0 = Bw + (size_t)(m0 + lr) * K + lc;
    const float* Bp1 = Bw + (size_t)(m0 + lr + 64) * K + lc;

    float4 ra0, ra1, rb0, rb1;
    float acc[8][8];
    #pragma unroll
    for (int i = 0; i < 8; i++)
        #pragma unroll
        for (int j = 0; j < 8; j++) acc[i][j] = 0.f;

    // prologue: load tile 0
    ra0 = *(const float4*)(Ap0);
    ra1 = *(const float4*)(Ap1);
    rb0 = *(const float4*)(Bp0);
    rb1 = *(const float4*)(Bp1);
    {
        const float* pa0 = (const float*)&ra0;
        const float* pa1 = (const float*)&ra1;
        const float* pb0 = (const float*)&rb0;
        const float* pb1 = (const float*)&rb1;
        #pragma unroll
        for (int i = 0; i < 4; i++) {
            As[0][lc + i][lr]      = pa0[i];
            As[0][lc + i][lr + 64] = pa1[i];
            Bs[0][lc + i][lr]      = pb0[i];
            Bs[0][lc + i][lr + 64] = pb1[i];
        }
    }
    __syncthreads();

    int nk = K >> 4;
    for (int kt = 0; kt < nk; kt++) {
        int cur = kt & 1;
        if (kt + 1 < nk) {
            int k0 = (kt + 1) << 4;
            ra0 = *(const float4*)(Ap0 + k0);
            ra1 = *(const float4*)(Ap1 + k0);
            rb0 = *(const float4*)(Bp0 + k0);
            rb1 = *(const float4*)(Bp1 + k0);
        }
        #pragma unroll
        for (int kk = 0; kk < BK; kk++) {
            float a[8], b[8];
            *(float4*)(a)     = *(const float4*)&As[cur][kk][ty * 8];
            *(float4*)(a + 4) = *(const float4*)&As[cur][kk][ty * 8 + 4];
            *(float4*)(b)     = *(const float4*)&Bs[cur][kk][tx * 8];
            *(float4*)(b + 4) = *(const float4*)&Bs[cur][kk][tx * 8 + 4];
            #pragma unroll
            for (int i = 0; i < 8; i++)
                #pragma unroll
                for (int j = 0; j < 8; j++)
                    acc[i][j] = fmaf(a[i], b[j], acc[i][j]);
        }
        if (kt + 1 < nk) {
            int nxt = cur ^ 1;
            const float* pa0 = (const float*)&ra0;
            const float* pa1 = (const float*)&ra1;
            const float* pb0 = (const float*)&rb0;
            const float* pb1 = (const float*)&rb1;
            #pragma unroll
            for (int i = 0; i < 4; i++) {
                As[nxt][lc + i][lr]      = pa0[i];
                As[nxt][lc + i][lr + 64] = pa1[i];
                Bs[nxt][lc + i][lr]      = pb0[i];
                Bs[nxt][lc + i][lr + 64] = pb1[i];
            }
            __syncthreads();
        }
    }
    #pragma unroll
    for (int i = 0; i < 8; i++) {
        float* Cr = C + (size_t)(n0 + ty * 8 + i) * M + m0 + tx * 8;
        *(float4*)(Cr)     = make_float4(acc[i][0], acc[i][1], acc[i][2], acc[i][3]);
        *(float4*)(Cr + 4) = make_float4(acc[i][4], acc[i][5], acc[i][6], acc[i][7]);
    }
}

__global__ void __launch_bounds__(256) k_gemm_x(const float* __restrict__ x,
                                                const float* __restrict__ Wp) {
    gemm_nt_dev(x, Wp, g_P, NT, 3 * D_, D_);
}
__global__ void __launch_bounds__(256) k_gemm_i(const float* __restrict__ Wi) {
    gemm_nt_dev(g_integral, Wi, g_I, NT, 3 * D_, D_);
}
__global__ void __launch_bounds__(256) k_gemm_d(const float* __restrict__ Wd) {
    gemm_nt_dev(g_deriv, Wd, g_Dm, NT, 3 * D_, D_);
}
__global__ void __launch_bounds__(256) k_gemm_o(const float* __restrict__ ow,
                                                float* __restrict__ out) {
    gemm_nt_dev(g_attn, ow, out, NT, D_, D_);
}

// ---------------- 5) gate combine -> q,k,v ----------------------------------
__global__ void k_combine() {
    int idx = blockIdx.x * blockDim.x + threadIdx.x;   // NT*D threads
    int n = idx >> 10, o = idx & 1023;
    const float* gg = g_gates + n * 9;
    #pragma unroll
    for (int p = 0; p < 3; p++) {
        size_t off = (size_t)n * 3072 + p * 1024 + o;
        float val = gg[p * 3 + 0] * g_P[off]
                  + gg[p * 3 + 1] * g_I[off]
                  + gg[p * 3 + 2] * (g_Dm[off] + g_kick[n * 3 + p] * g_wkick[p * 1024 + o]);
        float* dst = (p == 0) ? g_q : (p == 1) ? g_k : g_v;
        dst[(size_t)n * 1024 + o] = val;
    }
}

// ---------------- 6) sparse dilated attention -------------------------------
// one warp per (token, head); <=13 active positions of the 15 slots.
__global__ void k_attn(const int* __restrict__ positions, int adim) {
    int n = blockIdx.x;
    int b = n / T_, t = n % T_;
    int h = threadIdx.x >> 5;
    int lane = threadIdx.x & 31;

    int cnt = 1 + min(t, 3);
    for (int kk = 4; kk <= t; kk <<= 1) cnt++;   // dilated 2^k offsets

    const float* qr = g_q + (size_t)n * D_ + h * DH;
    float2 qv = *(const float2*)(qr + lane * 2);

    int pos[AMAX];
    float sc[AMAX];
    #pragma unroll
    for (int a = 0; a < AMAX; a++) {
        if (a < cnt) {
            pos[a] = positions[t * adim + a];
            const float* kr = g_k + (size_t)(b * T_ + pos[a]) * D_ + h * DH;
            float2 kv = *(const float2*)(kr + lane * 2);
            float s = qv.x * kv.x + qv.y * kv.y;
            #pragma unroll
            for (int off = 16; off; off >>= 1) s += __shfl_xor_sync(~0u, s, off);
            sc[a] = s * 0.125f;                  // D_HEAD^-0.5
        } else {
            pos[a] = 0;
            sc[a] = NEGF;
        }
    }
    float m = NEGF;
    #pragma unroll
    for (int a = 0; a < AMAX; a++) m = fmaxf(m, sc[a]);
    float sum = 0.f;
    #pragma unroll
    for (int a = 0; a < AMAX; a++) {
        sc[a] = (a < cnt) ? expf(sc[a] - m) : 0.f;
        sum += sc[a];
    }
    float inv = 1.f / sum;
    float2 acc = make_float2(0.f, 0.f);
    #pragma unroll
    for (int a = 0; a < AMAX; a++) {
        if (a < cnt) {
            const float* vr = g_v + (size_t)(b * T_ + pos[a]) * D_ + h * DH;
            float2 vv = *(const float2*)(vr + lane * 2);
            float w = sc[a] * inv;
            acc.x += w * vv.x;
            acc.y += w * vv.y;
        }
    }
    *(float2*)(g_attn + (size_t)n * D_ + h * DH + lane * 2) = acc;
}

// ---------------- launch -----------------------------------------------------
extern "C" void kernel_launch(void* const* d_in, const int* in_sizes, int n_in,
                              void* d_out, int out_size) {
    const float* x      = (const float*)d_in[0];
    const float* Wp     = (const float*)d_in[1];
    const float* Wi     = (const float*)d_in[2];
    const float* Wd     = (const float*)d_in[3];
    const float* gate_w = (const float*)d_in[4];
    const float* gate_b = (const float*)d_in[5];
    const float* kick_v = (const float*)d_in[6];
    const float* kick_w = (const float*)d_in[7];
    const float* kick_b = (const float*)d_in[8];
    const float* o_w    = (const float*)d_in[9];
    const int* positions = (const int*)d_in[10];
    int adim = in_sizes[10] / T_;    // 15

    k_scan<<<dim3(D_ / 256, B_), 256>>>(x);
    k_stats<<<NT, 256>>>(x, gate_w, gate_b, kick_w, kick_b);
    k_wkick<<<(3 * D_ * 32) / 256, 256>>>(Wd, kick_v);

    dim3 gproj(3 * D_ / 128, NT / 128);   // 24 x 32
    k_gemm_x<<<gproj, 256>>>(x, Wp);
    k_gemm_i<<<gproj, 256>>>(Wi);
    k_gemm_d<<<gproj, 256>>>(Wd);

    k_combine<<<(NT * D_) / 256, 256>>>();
    k_attn<<<NT, 512>>>(positions, adim);

    dim3 gout(D_ / 128, NT / 128);        // 8 x 32
    k_gemm_o<<<gout, 256>>>(o_w, (float*)d_out);
}

// round 13
// speedup vs baseline: 1.8306x; 1.8306x over previous
#include <cuda_runtime.h>
#include <cuda_bf16.h>
#include <cstdint>

#define B_ 2
#define T_ 2048
#define D_ 1024
#define NT (B_*T_)          // 4096
#define NH 16
#define DH 64
#define AMAX 15
#define NEGF (-1e30f)
#define CH 16               // scan chunks
#define CL (T_/CH)          // 128
#define LOG2_095 (-0.07400058003f)   // log2(0.95)
#define P128 (0.0014080610f)         // 0.95^128

// ---------------- scratch (device-side only; NEVER passed from host) ---------
__device__ float g_gates[NT*9];
__device__ float g_kick[NT*3];
__device__ float g_Ilocal[(size_t)NT*D_];
__device__ float g_cend[B_*CH*D_];
__device__ float g_cin[B_*CH*D_];
__device__ __nv_bfloat16 g_Abh[(size_t)NT*3*D_];    // A hi (reused per p; also attn-out)
__device__ __nv_bfloat16 g_Abl[(size_t)NT*3*D_];    // A lo
__device__ __nv_bfloat16 g_Bbh[(size_t)D_*3*D_];    // B hi (reused per p; also o_w)
__device__ __nv_bfloat16 g_Bbl[(size_t)D_*3*D_];    // B lo
__device__ float g_qkv[(size_t)3*NT*D_];            // q,k,v

// ---------------- PTX helpers (macros only) ----------------------------------
__device__ __forceinline__ uint32_t cvta_smem(const void* p){
    uint32_t a;
    asm("{ .reg .u64 t; cvta.to.shared.u64 t, %1; cvt.u32.u64 %0, t; }":"=r"(a):"l"(p));
    return a;
}
__device__ __forceinline__ void cpasync16(uint32_t dst, const void* src){
    asm volatile("cp.async.cg.shared.global [%0],[%1],16;"::"r"(dst),"l"(src));
}
__device__ __forceinline__ void cp_commit(){ asm volatile("cp.async.commit_group;":::"memory"); }
template<int N> __device__ __forceinline__ void cp_wait(){
    asm volatile("cp.async.wait_group %0;"::"n"(N):"memory");
}
#define LDSM4(r0,r1,r2,r3,addr) \
    asm volatile("ldmatrix.sync.aligned.m8n8.x4.shared.b16 {%0,%1,%2,%3}, [%4];" \
        : "=r"(r0),"=r"(r1),"=r"(r2),"=r"(r3) : "r"(addr))
#define LDSM2(r0,r1,addr) \
    asm volatile("ldmatrix.sync.aligned.m8n8.x2.shared.b16 {%0,%1}, [%2];" \
        : "=r"(r0),"=r"(r1) : "r"(addr))
#define MMA16816(c0,c1,c2,c3,a0,a1,a2,a3,b0,b1) \
    asm volatile("mma.sync.aligned.m16n8k16.row.col.f32.bf16.bf16.f32 " \
        "{%0,%1,%2,%3}, {%4,%5,%6,%7}, {%8,%9}, {%0,%1,%2,%3};" \
        : "+f"(c0),"+f"(c1),"+f"(c2),"+f"(c3) \
        : "r"(a0),"r"(a1),"r"(a2),"r"(a3),"r"(b0),"r"(b1))
// 3-term split product: ah*bh + ah*bl + al*bh
#define MMA3(c, ah_, al_, bh_, bl_) do { \
    MMA16816(c.x,c.y,c.z,c.w, ah_.x,ah_.y,ah_.z,ah_.w, bh_.x,bh_.y); \
    MMA16816(c.x,c.y,c.z,c.w, ah_.x,ah_.y,ah_.z,ah_.w, bl_.x,bl_.y); \
    MMA16816(c.x,c.y,c.z,c.w, al_.x,al_.y,al_.z,al_.w, bh_.x,bh_.y); \
} while(0)

// ---------------- 1) per-token stats -----------------------------------------
__global__ void k_stats(const float* __restrict__ x,
                        const float* __restrict__ gate_w,
                        const float* __restrict__ gate_b,
                        const float* __restrict__ kick_w,
                        const float* __restrict__ kick_b) {
    int n = blockIdx.x;
    int t = n % T_;
    int tid = threadIdx.x;
    const float* xr = x + (size_t)n * D_;
    const float* xp = xr - D_;

    float s[15];
    #pragma unroll
    for (int i = 0; i < 15; i++) s[i] = 0.f;
    for (int d = tid; d < D_; d += 256) {
        float xv = xr[d];
        float pv = (t > 0) ? xp[d] : 0.f;
        s[0] += xv * xv; s[1] += pv * pv; s[2] += xv * pv;
        #pragma unroll
        for (int j = 0; j < 9; j++) s[3 + j] += xv * gate_w[j * D_ + d];
        #pragma unroll
        for (int p = 0; p < 3; p++) s[12 + p] += xv * kick_w[p * D_ + d];
    }
    #pragma unroll
    for (int i = 0; i < 15; i++)
        for (int off = 16; off; off >>= 1) s[i] += __shfl_xor_sync(~0u, s[i], off);

    __shared__ float red[8][15];
    int w = tid >> 5, l = tid & 31;
    if (l == 0) {
        #pragma unroll
        for (int i = 0; i < 15; i++) red[w][i] = s[i];
    }
    __syncthreads();
    if (tid == 0) {
        float f[15];
        #pragma unroll
        for (int i = 0; i < 15; i++) {
            float a = 0.f;
            #pragma unroll
            for (int w2 = 0; w2 < 8; w2++) a += red[w2][i];
            f[i] = a;
        }
        float n1 = fmaxf(sqrtf(f[0]), 1e-12f);
        float n2 = fmaxf(sqrtf(f[1]), 1e-12f);
        float cosv = (t > 0) ? f[2] / (n1 * n2) : 0.f;
        float stag = (cosv > 0.95f) ? 1.f : 0.f;
        #pragma unroll
        for (int p = 0; p < 3; p++) {
            float l0 = f[3+p*3+0] + gate_b[p*3+0];
            float l1 = f[3+p*3+1] + gate_b[p*3+1];
            float l2 = f[3+p*3+2] + gate_b[p*3+2];
            float m = fmaxf(l0, fmaxf(l1, l2));
            float e0 = expf(l0-m), e1 = expf(l1-m), e2 = expf(l2-m);
            float inv = 1.f / (e0+e1+e2);
            float g0 = fminf(e0*inv, 0.6f);
            float g1 = fmaxf(fminf(e1*inv, 0.6f), 0.25f);
            float g2 = fminf(e2*inv, 0.6f);
            float inv2 = 1.f / (g0+g1+g2);
            g_gates[n*9+p*3+0] = g0*inv2;
            g_gates[n*9+p*3+1] = g1*inv2;
            g_gates[n*9+p*3+2] = g2*inv2;
            float ks = 1.f / (1.f + expf(-(f[12+p] + kick_b[p])));
            g_kick[n*3+p] = stag * ks;
        }
    }
}

// ---------------- 2) chunked EMA scan ----------------------------------------
__global__ void k_scan1(const float* __restrict__ x) {
    int d = blockIdx.x * 256 + threadIdx.x;
    int c = blockIdx.y, b = blockIdx.z;
    const float* xb = x + ((size_t)(b*T_ + c*CL))*D_ + d;
    float* Ib = g_Ilocal + ((size_t)(b*T_ + c*CL))*D_ + d;
    float L; int t0;
    if (c == 0) { L = xb[0]; Ib[0] = L; t0 = 1; }
    else { L = 0.f; t0 = 0; }
    for (int t = t0; t < CL; t++) {
        L = 0.95f*L + 0.05f*xb[(size_t)t*D_];
        Ib[(size_t)t*D_] = L;
    }
    g_cend[(b*CH + c)*D_ + d] = L;
}

__global__ void k_scan2() {
    int d = blockIdx.x * 256 + threadIdx.x;
    int b = blockIdx.y;
    float I = g_cend[(b*CH + 0)*D_ + d];
    g_cin[(b*CH + 0)*D_ + d] = 0.f;
    for (int c = 1; c < CH; c++) {
        g_cin[(b*CH + c)*D_ + d] = I;
        I = g_cend[(b*CH + c)*D_ + d] + P128 * I;
    }
}

// ---------------- 3) split-bf16 operand builders ------------------------------
__device__ __forceinline__ void split_bf(float v, __nv_bfloat16* H, __nv_bfloat16* L, size_t i){
    __nv_bfloat16 h = __float2bfloat16_rn(v);
    H[i] = h;
    L[i] = __float2bfloat16_rn(v - __bfloat162float(h));
}

// A'' for projection p: [n][ g0*x | g1*I | g2*(dx + kick*kick_v) ]  (K'=3072)
__global__ void k_buildA(const float* __restrict__ x, const float* __restrict__ kick_v,
                         int p) {
    int n = blockIdx.x;
    int b = n / T_, t = n % T_;
    int c = t / CL;
    float pfac = exp2f((float)((t % CL) + 1) * LOG2_095);   // 0.95^(tm+1)
    float gg0 = g_gates[n*9 + p*3 + 0];
    float gg1 = g_gates[n*9 + p*3 + 1];
    float gg2 = g_gates[n*9 + p*3 + 2];
    float kk  = g_kick[n*3 + p];
    size_t base = (size_t)n * (3*D_);
    for (int d = threadIdx.x; d < D_; d += 256) {
        float xv = x[(size_t)n*D_ + d];
        float dv = (t > 0) ? (xv - x[(size_t)(n-1)*D_ + d]) : 0.f;
        float Iv = g_Ilocal[(size_t)n*D_ + d] + pfac * g_cin[(b*CH + c)*D_ + d];
        split_bf(gg0*xv, g_Abh, g_Abl, base + d);
        split_bf(gg1*Iv, g_Abh, g_Abl, base + D_ + d);
        split_bf(gg2*(dv + kk*kick_v[p*D_ + d]), g_Abh, g_Abl, base + 2*D_ + d);
    }
}

// B'' for projection p: row o = [ Wp_p[o] | Wi_p[o] | Wd_p[o] ]
__global__ void k_buildB(const float* __restrict__ Wp, const float* __restrict__ Wi,
                         const float* __restrict__ Wd, int p) {
    int o = blockIdx.x;
    size_t base = (size_t)o * (3*D_);
    size_t wsrc = (size_t)(p*D_ + o) * D_;
    for (int d = threadIdx.x; d < D_; d += 256) {
        split_bf(Wp[wsrc + d], g_Bbh, g_Bbl, base + d);
        split_bf(Wi[wsrc + d], g_Bbh, g_Bbl, base + D_ + d);
        split_bf(Wd[wsrc + d], g_Bbh, g_Bbl, base + 2*D_ + d);
    }
}

// split o_w into the B buffers (device-side targets; no symbols from host)
__global__ void k_split_ow(const float* __restrict__ src, int nElem) {
    int i = blockIdx.x * 256 + threadIdx.x;
    if (i < nElem) split_bf(src[i], g_Bbh, g_Bbl, i);
}

// ---------------- 4) bf16 mma.sync GEMM — fully scalarized -------------------
// Block tile 128(M) x 64(N), BK=16, 8 warps (4x2), warp tile 32x32.
// C = Ah*Bh^T + Ah*Bl^T + Al*Bh^T, fp32 acc. Operands are the g_* buffers,
// resolved INSIDE device code. Output: d_out if useExt, else g_qkv slice p.
#define BKq 16
#define APADq 24                        // 48 B rows: 16B-aligned, ldmatrix-clean
#define A_EL (128*APADq)                // 3072 elems
#define B_EL (64*APADq)                 // 1536 elems
#define STG (2*A_EL + 2*B_EL)           // 9216 elems (18432 B) per stage

#define EPI(c, mi, ni) do { \
    int r0 = m0 + warp_m*32 + (mi)*16 + (lane >> 2); \
    int cc = n0 + warp_n*32 + (ni)*8 + (lane & 3)*2; \
    *(float2*)(C + (size_t)r0*1024 + cc)     = make_float2(c.x, c.y); \
    *(float2*)(C + (size_t)(r0+8)*1024 + cc) = make_float2(c.z, c.w); \
} while(0)

__global__ void __launch_bounds__(256,1) k_gemm(float* __restrict__ Cext,
                                                int p, int K, int useExt)
{
    const __nv_bfloat16* Ah = g_Abh;
    const __nv_bfloat16* Al = g_Abl;
    const __nv_bfloat16* Bh = g_Bbh;
    const __nv_bfloat16* Bl = g_Bbl;
    float* C = useExt ? Cext : (g_qkv + (size_t)p*NT*D_);

    __shared__ __align__(16) __nv_bfloat16 smarr[2*STG];
    uint32_t smb = cvta_smem(smarr);
    int tid = threadIdx.x, lane = tid & 31, wid = tid >> 5;
    int warp_m = wid >> 1, warp_n = wid & 1;      // 4 x 2 warps
    int n0 = blockIdx.x * 64;
    int m0 = blockIdx.y * 128;

    float4 z4 = make_float4(0.f, 0.f, 0.f, 0.f);
    float4 c00 = z4, c01 = z4, c02 = z4, c03 = z4;
    float4 c10 = z4, c11 = z4, c12 = z4, c13 = z4;

    // loader mapping: 3 cp.async per thread per stage
    int arow_l = tid >> 1;              // 0..127
    int au     = (tid & 1) * 8;         // elem offset 0/8
    int brow_l = (tid & 127) >> 1;      // 0..63
    const __nv_bfloat16* Bsrc = (tid >= 128) ? Bl : Bh;
    uint32_t bArr = 2*A_EL + ((tid >= 128) ? B_EL : 0);

    const __nv_bfloat16* pAh = Ah + (size_t)(m0 + arow_l)*K + au;
    const __nv_bfloat16* pAl = Al + (size_t)(m0 + arow_l)*K + au;
    const __nv_bfloat16* pB  = Bsrc + (size_t)(n0 + brow_l)*K + au;
    uint32_t sAh = (uint32_t)(arow_l*APADq + au);
    uint32_t sAl = (uint32_t)(A_EL + arow_l*APADq + au);
    uint32_t sB  = (uint32_t)(bArr + brow_l*APADq + au);

    int NKB = K / BKq;

    cpasync16(smb + sAh*2u, pAh);
    cpasync16(smb + sAl*2u, pAl);
    cpasync16(smb + sB*2u,  pB);
    cp_commit();

    // ldmatrix lane addressing (constant per thread)
    int arow = warp_m*32 + (lane & 15);
    int acol = (lane >> 4) * 8;
    uint32_t offA0 = (uint32_t)(arow*APADq + acol) * 2u;
    uint32_t offA1 = (uint32_t)((arow + 16)*APADq + acol) * 2u;
    int brow = warp_n*32 + (lane & 7);
    int bcol = ((lane >> 3) & 1) * 8;
    uint32_t offB0 = (uint32_t)(brow*APADq + bcol) * 2u;
    uint32_t offB1 = (uint32_t)((brow + 8)*APADq + bcol) * 2u;
    uint32_t offB2 = (uint32_t)((brow + 16)*APADq + bcol) * 2u;
    uint32_t offB3 = (uint32_t)((brow + 24)*APADq + bcol) * 2u;

    for (int kb = 0; kb < NKB; kb++) {
        int s = kb & 1;
        if (kb + 1 < NKB) {
            uint32_t so = (uint32_t)((s ^ 1) * STG);
            int ko = (kb + 1) * BKq;
            cpasync16(smb + (so + sAh)*2u, pAh + ko);
            cpasync16(smb + (so + sAl)*2u, pAl + ko);
            cpasync16(smb + (so + sB)*2u,  pB + ko);
            cp_commit();
            cp_wait<1>();
        } else {
            cp_wait<0>();
        }
        __syncthreads();

        uint32_t sb2 = (uint32_t)(s * STG) * 2u;
        uint32_t aH = smb + sb2;
        uint32_t aL = aH + A_EL*2u;
        uint32_t bH = aL + A_EL*2u;
        uint32_t bL = bH + B_EL*2u;

        uint4 a0h, a1h, a0l, a1l;
        uint2 b0h, b1h, b2h, b3h, b0l, b1l, b2l, b3l;
        LDSM4(a0h.x, a0h.y, a0h.z, a0h.w, aH + offA0);
        LDSM4(a1h.x, a1h.y, a1h.z, a1h.w, aH + offA1);
        LDSM4(a0l.x, a0l.y, a0l.z, a0l.w, aL + offA0);
        LDSM4(a1l.x, a1l.y, a1l.z, a1l.w, aL + offA1);
        LDSM2(b0h.x, b0h.y, bH + offB0);
        LDSM2(b1h.x, b1h.y, bH + offB1);
        LDSM2(b2h.x, b2h.y, bH + offB2);
        LDSM2(b3h.x, b3h.y, bH + offB3);
        LDSM2(b0l.x, b0l.y, bL + offB0);
        LDSM2(b1l.x, b1l.y, bL + offB1);
        LDSM2(b2l.x, b2l.y, bL + offB2);
        LDSM2(b3l.x, b3l.y, bL + offB3);

        MMA3(c00, a0h, a0l, b0h, b0l);
        MMA3(c01, a0h, a0l, b1h, b1l);
        MMA3(c02, a0h, a0l, b2h, b2l);
        MMA3(c03, a0h, a0l, b3h, b3l);
        MMA3(c10, a1h, a1l, b0h, b0l);
        MMA3(c11, a1h, a1l, b1h, b1l);
        MMA3(c12, a1h, a1l, b2h, b2l);
        MMA3(c13, a1h, a1l, b3h, b3l);

        __syncthreads();
    }

    EPI(c00, 0, 0); EPI(c01, 0, 1); EPI(c02, 0, 2); EPI(c03, 0, 3);
    EPI(c10, 1, 0); EPI(c11, 1, 1); EPI(c12, 1, 2); EPI(c13, 1, 3);
}

// ---------------- 5) sparse dilated attention (writes split-bf16 out) --------
__global__ void k_attn(const int* __restrict__ positions, int adim) {
    const float* gq = g_qkv;
    const float* gk = g_qkv + (size_t)NT*D_;
    const float* gv = g_qkv + (size_t)2*NT*D_;
    int n = blockIdx.x;
    int b = n / T_, t = n % T_;
    int h = threadIdx.x >> 5;
    int lane = threadIdx.x & 31;

    int cnt = 1 + min(t, 3);
    for (int kk = 4; kk <= t; kk <<= 1) cnt++;

    const float* qr = gq + (size_t)n*D_ + h*DH;
    float2 qv = *(const float2*)(qr + lane*2);

    int pos[AMAX];
    float sc[AMAX];
    #pragma unroll
    for (int a = 0; a < AMAX; a++) {
        if (a < cnt) {
            pos[a] = positions[t*adim + a];
            const float* kr = gk + (size_t)(b*T_ + pos[a])*D_ + h*DH;
            float2 kv = *(const float2*)(kr + lane*2);
            float s = qv.x*kv.x + qv.y*kv.y;
            #pragma unroll
            for (int off = 16; off; off >>= 1) s += __shfl_xor_sync(~0u, s, off);
            sc[a] = s * 0.125f;
        } else { pos[a] = 0; sc[a] = NEGF; }
    }
    float m = NEGF;
    #pragma unroll
    for (int a = 0; a < AMAX; a++) m = fmaxf(m, sc[a]);
    float sum = 0.f;
    #pragma unroll
    for (int a = 0; a < AMAX; a++) {
        sc[a] = (a < cnt) ? expf(sc[a] - m) : 0.f;
        sum += sc[a];
    }
    float inv = 1.f / sum;
    float2 acc = make_float2(0.f, 0.f);
    #pragma unroll
    for (int a = 0; a < AMAX; a++) {
        if (a < cnt) {
            const float* vr = gv + (size_t)(b*T_ + pos[a])*D_ + h*DH;
            float2 vv = *(const float2*)(vr + lane*2);
            float w = sc[a]*inv;
            acc.x += w*vv.x; acc.y += w*vv.y;
        }
    }
    size_t oidx = (size_t)n*D_ + h*DH + lane*2;
    split_bf(acc.x, g_Abh, g_Abl, oidx);
    split_bf(acc.y, g_Abh, g_Abl, oidx + 1);
}

// ---------------- launch ------------------------------------------------------
// NOTE: only harness pointers and plain ints cross the host->kernel boundary.
extern "C" void kernel_launch(void* const* d_in, const int* in_sizes, int n_in,
                              void* d_out, int out_size) {
    const float* x      = (const float*)d_in[0];
    const float* Wp     = (const float*)d_in[1];
    const float* Wi     = (const float*)d_in[2];
    const float* Wd     = (const float*)d_in[3];
    const float* gate_w = (const float*)d_in[4];
    const float* gate_b = (const float*)d_in[5];
    const float* kick_v = (const float*)d_in[6];
    const float* kick_w = (const float*)d_in[7];
    const float* kick_b = (const float*)d_in[8];
    const float* o_w    = (const float*)d_in[9];
    const int* positions = (const int*)d_in[10];
    int adim = in_sizes[10] / T_;

    k_stats<<<NT, 256>>>(x, gate_w, gate_b, kick_w, kick_b);
    k_scan1<<<dim3(D_/256, CH, B_), 256>>>(x);
    k_scan2<<<dim3(D_/256, B_), 256>>>();

    // q,k,v: one fused GEMM per projection (M=4096, N=1024, K'=3072)
    for (int p = 0; p < 3; p++) {
        k_buildA<<<NT, 256>>>(x, kick_v, p);
        k_buildB<<<D_, 256>>>(Wp, Wi, Wd, p);
        k_gemm<<<dim3(D_/64, NT/128), 256>>>(nullptr, p, 3*D_, 0);
    }

    k_attn<<<NT, 512>>>(positions, adim);          // writes split-bf16 into g_Ab*
    k_split_ow<<<(D_*D_)/256, 256>>>(o_w, D_*D_);

    // out = attn @ o_w^T  (M=4096, N=1024, K=1024)
    k_gemm<<<dim3(D_/64, NT/128), 256>>>((float*)d_out, 0, D_, 1);
}

// round 14
// speedup vs baseline: 2.6433x; 1.4439x over previous
#include <cuda_runtime.h>
#include <cuda_bf16.h>
#include <cstdint>

#define B_ 2
#define T_ 2048
#define D_ 1024
#define NT (B_*T_)          // 4096
#define NH 16
#define DH 64
#define AMAX 15
#define NEGF (-1e30f)
#define CH 16               // scan chunks
#define CL (T_/CH)          // 128
#define LOG2_095 (-0.07400058003f)   // log2(0.95)
#define P128 (0.0014080610f)         // 0.95^128

// ---------------- scratch (device-side only; NEVER passed from host) ---------
__device__ float g_gates[NT*9];
__device__ float g_kick[NT*3];
__device__ float g_Ilocal[(size_t)NT*D_];
__device__ float g_cend[B_*CH*D_];
__device__ float g_cin[B_*CH*D_];
__device__ __nv_bfloat16 g_Abh[(size_t)3*NT*3*D_];  // A hi, all 3 projections (also attn-out)
__device__ __nv_bfloat16 g_Abl[(size_t)3*NT*3*D_];  // A lo
__device__ __nv_bfloat16 g_Bbh[(size_t)3*D_*3*D_];  // B hi, all 3 projections (also o_w)
__device__ __nv_bfloat16 g_Bbl[(size_t)3*D_*3*D_];  // B lo
__device__ float g_qkv[(size_t)3*NT*D_];            // q,k,v

// ---------------- PTX helpers (macros only) ----------------------------------
__device__ __forceinline__ uint32_t cvta_smem(const void* p){
    uint32_t a;
    asm("{ .reg .u64 t; cvta.to.shared.u64 t, %1; cvt.u32.u64 %0, t; }":"=r"(a):"l"(p));
    return a;
}
__device__ __forceinline__ void cpasync16(uint32_t dst, const void* src){
    asm volatile("cp.async.cg.shared.global [%0],[%1],16;"::"r"(dst),"l"(src));
}
__device__ __forceinline__ void cp_commit(){ asm volatile("cp.async.commit_group;":::"memory"); }
template<int N> __device__ __forceinline__ void cp_wait(){
    asm volatile("cp.async.wait_group %0;"::"n"(N):"memory");
}
#define LDSM4(r0,r1,r2,r3,addr) \
    asm volatile("ldmatrix.sync.aligned.m8n8.x4.shared.b16 {%0,%1,%2,%3}, [%4];" \
        : "=r"(r0),"=r"(r1),"=r"(r2),"=r"(r3) : "r"(addr))
#define LDSM2(r0,r1,addr) \
    asm volatile("ldmatrix.sync.aligned.m8n8.x2.shared.b16 {%0,%1}, [%2];" \
        : "=r"(r0),"=r"(r1) : "r"(addr))
#define MMA16816(c0,c1,c2,c3,a0,a1,a2,a3,b0,b1) \
    asm volatile("mma.sync.aligned.m16n8k16.row.col.f32.bf16.bf16.f32 " \
        "{%0,%1,%2,%3}, {%4,%5,%6,%7}, {%8,%9}, {%0,%1,%2,%3};" \
        : "+f"(c0),"+f"(c1),"+f"(c2),"+f"(c3) \
        : "r"(a0),"r"(a1),"r"(a2),"r"(a3),"r"(b0),"r"(b1))
// 3-term split product: ah*bh + ah*bl + al*bh
#define MMA3(c, ah_, al_, bh_, bl_) do { \
    MMA16816(c.x,c.y,c.z,c.w, ah_.x,ah_.y,ah_.z,ah_.w, bh_.x,bh_.y); \
    MMA16816(c.x,c.y,c.z,c.w, ah_.x,ah_.y,ah_.z,ah_.w, bl_.x,bl_.y); \
    MMA16816(c.x,c.y,c.z,c.w, al_.x,al_.y,al_.z,al_.w, bh_.x,bh_.y); \
} while(0)

// ---------------- 1) per-token stats -----------------------------------------
__global__ void k_stats(const float* __restrict__ x,
                        const float* __restrict__ gate_w,
                        const float* __restrict__ gate_b,
                        const float* __restrict__ kick_w,
                        const float* __restrict__ kick_b) {
    int n = blockIdx.x;
    int t = n % T_;
    int tid = threadIdx.x;
    const float* xr = x + (size_t)n * D_;
    const float* xp = xr - D_;

    float s[15];
    #pragma unroll
    for (int i = 0; i < 15; i++) s[i] = 0.f;
    for (int d = tid; d < D_; d += 256) {
        float xv = xr[d];
        float pv = (t > 0) ? xp[d] : 0.f;
        s[0] += xv * xv; s[1] += pv * pv; s[2] += xv * pv;
        #pragma unroll
        for (int j = 0; j < 9; j++) s[3 + j] += xv * gate_w[j * D_ + d];
        #pragma unroll
        for (int p = 0; p < 3; p++) s[12 + p] += xv * kick_w[p * D_ + d];
    }
    #pragma unroll
    for (int i = 0; i < 15; i++)
        for (int off = 16; off; off >>= 1) s[i] += __shfl_xor_sync(~0u, s[i], off);

    __shared__ float red[8][15];
    int w = tid >> 5, l = tid & 31;
    if (l == 0) {
        #pragma unroll
        for (int i = 0; i < 15; i++) red[w][i] = s[i];
    }
    __syncthreads();
    if (tid == 0) {
        float f[15];
        #pragma unroll
        for (int i = 0; i < 15; i++) {
            float a = 0.f;
            #pragma unroll
            for (int w2 = 0; w2 < 8; w2++) a += red[w2][i];
            f[i] = a;
        }
        float n1 = fmaxf(sqrtf(f[0]), 1e-12f);
        float n2 = fmaxf(sqrtf(f[1]), 1e-12f);
        float cosv = (t > 0) ? f[2] / (n1 * n2) : 0.f;
        float stag = (cosv > 0.95f) ? 1.f : 0.f;
        #pragma unroll
        for (int p = 0; p < 3; p++) {
            float l0 = f[3+p*3+0] + gate_b[p*3+0];
            float l1 = f[3+p*3+1] + gate_b[p*3+1];
            float l2 = f[3+p*3+2] + gate_b[p*3+2];
            float m = fmaxf(l0, fmaxf(l1, l2));
            float e0 = expf(l0-m), e1 = expf(l1-m), e2 = expf(l2-m);
            float inv = 1.f / (e0+e1+e2);
            float g0 = fminf(e0*inv, 0.6f);
            float g1 = fmaxf(fminf(e1*inv, 0.6f), 0.25f);
            float g2 = fminf(e2*inv, 0.6f);
            float inv2 = 1.f / (g0+g1+g2);
            g_gates[n*9+p*3+0] = g0*inv2;
            g_gates[n*9+p*3+1] = g1*inv2;
            g_gates[n*9+p*3+2] = g2*inv2;
            float ks = 1.f / (1.f + expf(-(f[12+p] + kick_b[p])));
            g_kick[n*3+p] = stag * ks;
        }
    }
}

// ---------------- 2) chunked EMA scan ----------------------------------------
__global__ void k_scan1(const float* __restrict__ x) {
    int d = blockIdx.x * 256 + threadIdx.x;
    int c = blockIdx.y, b = blockIdx.z;
    const float* xb = x + ((size_t)(b*T_ + c*CL))*D_ + d;
    float* Ib = g_Ilocal + ((size_t)(b*T_ + c*CL))*D_ + d;
    float L; int t0;
    if (c == 0) { L = xb[0]; Ib[0] = L; t0 = 1; }
    else { L = 0.f; t0 = 0; }
    for (int t = t0; t < CL; t++) {
        L = 0.95f*L + 0.05f*xb[(size_t)t*D_];
        Ib[(size_t)t*D_] = L;
    }
    g_cend[(b*CH + c)*D_ + d] = L;
}

__global__ void k_scan2() {
    int d = blockIdx.x * 256 + threadIdx.x;
    int b = blockIdx.y;
    float I = g_cend[(b*CH + 0)*D_ + d];
    g_cin[(b*CH + 0)*D_ + d] = 0.f;
    for (int c = 1; c < CH; c++) {
        g_cin[(b*CH + c)*D_ + d] = I;
        I = g_cend[(b*CH + c)*D_ + d] + P128 * I;
    }
}

// ---------------- 3) split-bf16 operand builders ------------------------------
__device__ __forceinline__ void split_bf(float v, __nv_bfloat16* H, __nv_bfloat16* L, size_t i){
    __nv_bfloat16 h = __float2bfloat16_rn(v);
    H[i] = h;
    L[i] = __float2bfloat16_rn(v - __bfloat162float(h));
}

// A'' for ALL projections: [p][n][ g0*x | g1*I | g2*(dx + kick*kick_v) ]
__global__ void k_buildA(const float* __restrict__ x, const float* __restrict__ kick_v) {
    int n = blockIdx.x;
    int b = n / T_, t = n % T_;
    int c = t / CL;
    float pfac = exp2f((float)((t % CL) + 1) * LOG2_095);   // 0.95^(tm+1)
    __shared__ float gg[9], kk[3];
    if (threadIdx.x < 9) gg[threadIdx.x] = g_gates[n*9 + threadIdx.x];
    if (threadIdx.x < 3) kk[threadIdx.x] = g_kick[n*3 + threadIdx.x];
    __syncthreads();
    for (int d = threadIdx.x; d < D_; d += 256) {
        float xv = x[(size_t)n*D_ + d];
        float dv = (t > 0) ? (xv - x[(size_t)(n-1)*D_ + d]) : 0.f;
        float Iv = g_Ilocal[(size_t)n*D_ + d] + pfac * g_cin[(b*CH + c)*D_ + d];
        #pragma unroll
        for (int p = 0; p < 3; p++) {
            size_t base = ((size_t)p*NT + n) * (3*D_);
            split_bf(gg[p*3+0]*xv, g_Abh, g_Abl, base + d);
            split_bf(gg[p*3+1]*Iv, g_Abh, g_Abl, base + D_ + d);
            split_bf(gg[p*3+2]*(dv + kk[p]*kick_v[p*D_ + d]), g_Abh, g_Abl, base + 2*D_ + d);
        }
    }
}

// B'' for ALL projections: global row (p*1024+o) = [ Wp_p[o] | Wi_p[o] | Wd_p[o] ]
__global__ void k_buildB(const float* __restrict__ Wp, const float* __restrict__ Wi,
                         const float* __restrict__ Wd) {
    int row = blockIdx.x;                    // 0..3*D_-1
    size_t base = (size_t)row * (3*D_);
    size_t wsrc = (size_t)row * D_;
    for (int d = threadIdx.x; d < D_; d += 256) {
        split_bf(Wp[wsrc + d], g_Bbh, g_Bbl, base + d);
        split_bf(Wi[wsrc + d], g_Bbh, g_Bbl, base + D_ + d);
        split_bf(Wd[wsrc + d], g_Bbh, g_Bbl, base + 2*D_ + d);
    }
}

// split o_w into the start of the B buffers (after projection GEMMs are done)
__global__ void k_split_ow(const float* __restrict__ src, int nElem) {
    int i = blockIdx.x * 256 + threadIdx.x;
    if (i < nElem) split_bf(src[i], g_Bbh, g_Bbl, i);
}

// ---------------- 4) bf16 mma.sync GEMM — BK=32, 3-stage pipeline ------------
// Block tile 128(M) x 64(N), 8 warps (4x2), warp tile 32x32.
// C = Ah*Bh^T + Ah*Bl^T + Al*Bh^T, fp32 acc; ldc = 1024.
// blockIdx.z = projection p: A base = p*NT*K, B base = p*D_*K.
#define BKq 32
#define APADq 40                        // 80 B rows: conflict-free ldmatrix banking
#define A_EL (128*APADq)                // 5120 elems
#define B_EL (64*APADq)                 // 2560 elems
#define STG (2*A_EL + 2*B_EL)           // 15360 elems (30720 B) per stage
#define GEMM_SMEM (3*STG*2)             // 92160 B, 3 stages

#define EPI(c, mi, ni) do { \
    int r0 = m0 + warp_m*32 + (mi)*16 + (lane >> 2); \
    int cc = n0 + warp_n*32 + (ni)*8 + (lane & 3)*2; \
    *(float2*)(C + (size_t)r0*1024 + cc)     = make_float2(c.x, c.y); \
    *(float2*)(C + (size_t)(r0+8)*1024 + cc) = make_float2(c.z, c.w); \
} while(0)

#define LOADSTAGE(st, ko) do { \
    uint32_t so_ = (uint32_t)(st) * STG; \
    cpasync16(smb + (so_ + sA0)*2u,  pAh0 + (ko)); \
    cpasync16(smb + (so_ + sA1)*2u,  pAh1 + (ko)); \
    cpasync16(smb + (so_ + sAl0)*2u, pAl0 + (ko)); \
    cpasync16(smb + (so_ + sAl1)*2u, pAl1 + (ko)); \
    cpasync16(smb + (so_ + sBh)*2u,  pBh  + (ko)); \
    cpasync16(smb + (so_ + sBl)*2u,  pBl  + (ko)); \
    cp_commit(); \
} while(0)

__global__ void __launch_bounds__(256,2) k_gemm(float* __restrict__ Cext,
                                                int K, int useExt)
{
    int z = blockIdx.z;
    const __nv_bfloat16* Ah = g_Abh + (size_t)z*NT*K;
    const __nv_bfloat16* Al = g_Abl + (size_t)z*NT*K;
    const __nv_bfloat16* Bh = g_Bbh + (size_t)z*D_*K;
    const __nv_bfloat16* Bl = g_Bbl + (size_t)z*D_*K;
    float* C = useExt ? Cext : (g_qkv + (size_t)z*NT*D_);

    extern __shared__ __align__(16) __nv_bfloat16 smarr[];
    uint32_t smb = cvta_smem(smarr);
    int tid = threadIdx.x, lane = tid & 31, wid = tid >> 5;
    int warp_m = wid >> 1, warp_n = wid & 1;      // 4 x 2 warps
    int n0 = blockIdx.x * 64;
    int m0 = blockIdx.y * 128;

    float4 z4 = make_float4(0.f, 0.f, 0.f, 0.f);
    float4 c00 = z4, c01 = z4, c02 = z4, c03 = z4;
    float4 c10 = z4, c11 = z4, c12 = z4, c13 = z4;

    // loader mapping: 6 cp.async per thread per stage (BK=32 → 4 chunks/row)
    int lr = tid >> 2;                  // 0..63
    int u  = (tid & 3) * 8;             // elem offset 0,8,16,24

    const __nv_bfloat16* pAh0 = Ah + (size_t)(m0 + lr)*K + u;
    const __nv_bfloat16* pAh1 = Ah + (size_t)(m0 + lr + 64)*K + u;
    const __nv_bfloat16* pAl0 = Al + (size_t)(m0 + lr)*K + u;
    const __nv_bfloat16* pAl1 = Al + (size_t)(m0 + lr + 64)*K + u;
    const __nv_bfloat16* pBh  = Bh + (size_t)(n0 + lr)*K + u;
    const __nv_bfloat16* pBl  = Bl + (size_t)(n0 + lr)*K + u;
    uint32_t sA0  = (uint32_t)(lr*APADq + u);
    uint32_t sA1  = (uint32_t)((lr+64)*APADq + u);
    uint32_t sAl0 = A_EL + sA0;
    uint32_t sAl1 = A_EL + sA1;
    uint32_t sBh  = 2*A_EL + (uint32_t)(lr*APADq + u);
    uint32_t sBl  = sBh + B_EL;

    int NKB = K / BKq;                  // >= 32 always

    LOADSTAGE(0, 0);
    LOADSTAGE(1, BKq);

    // ldmatrix lane addressing (constant per thread; ks adds 16 elems)
    int arow = warp_m*32 + (lane & 15);
    int acol = (lane >> 4) * 8;
    int brow = warp_n*32 + (lane & 7);
    int bcol = ((lane >> 3) & 1) * 8;

    for (int kb = 0; kb < NKB; kb++) {
        if (kb + 1 < NKB) cp_wait<1>(); else cp_wait<0>();
        __syncthreads();
        if (kb + 2 < NKB) LOADSTAGE((kb + 2) % 3, (kb + 2) * BKq);

        uint32_t base = smb + (uint32_t)((kb % 3) * STG) * 2u;
        uint32_t aH = base;
        uint32_t aL = base + A_EL*2u;
        uint32_t bH = base + 2*A_EL*2u;
        uint32_t bL = bH + B_EL*2u;

        #pragma unroll
        for (int ks = 0; ks < 2; ks++) {
            uint32_t offA0 = (uint32_t)(arow*APADq + acol + ks*16) * 2u;
            uint32_t offA1 = (uint32_t)((arow + 16)*APADq + acol + ks*16) * 2u;
            uint32_t offB0 = (uint32_t)(brow*APADq + bcol + ks*16) * 2u;
            uint32_t offB1 = (uint32_t)((brow + 8)*APADq + bcol + ks*16) * 2u;
            uint32_t offB2 = (uint32_t)((brow + 16)*APADq + bcol + ks*16) * 2u;
            uint32_t offB3 = (uint32_t)((brow + 24)*APADq + bcol + ks*16) * 2u;

            uint4 a0h, a1h, a0l, a1l;
            uint2 b0h, b1h, b2h, b3h, b0l, b1l, b2l, b3l;
            LDSM4(a0h.x, a0h.y, a0h.z, a0h.w, aH + offA0);
            LDSM4(a1h.x, a1h.y, a1h.z, a1h.w, aH + offA1);
            LDSM4(a0l.x, a0l.y, a0l.z, a0l.w, aL + offA0);
            LDSM4(a1l.x, a1l.y, a1l.z, a1l.w, aL + offA1);
            LDSM2(b0h.x, b0h.y, bH + offB0);
            LDSM2(b1h.x, b1h.y, bH + offB1);
            LDSM2(b2h.x, b2h.y, bH + offB2);
            LDSM2(b3h.x, b3h.y, bH + offB3);
            LDSM2(b0l.x, b0l.y, bL + offB0);
            LDSM2(b1l.x, b1l.y, bL + offB1);
            LDSM2(b2l.x, b2l.y, bL + offB2);
            LDSM2(b3l.x, b3l.y, bL + offB3);

            MMA3(c00, a0h, a0l, b0h, b0l);
            MMA3(c01, a0h, a0l, b1h, b1l);
            MMA3(c02, a0h, a0l, b2h, b2l);
            MMA3(c03, a0h, a0l, b3h, b3l);
            MMA3(c10, a1h, a1l, b0h, b0l);
            MMA3(c11, a1h, a1l, b1h, b1l);
            MMA3(c12, a1h, a1l, b2h, b2l);
            MMA3(c13, a1h, a1l, b3h, b3l);
        }
        __syncthreads();
    }

    EPI(c00, 0, 0); EPI(c01, 0, 1); EPI(c02, 0, 2); EPI(c03, 0, 3);
    EPI(c10, 1, 0); EPI(c11, 1, 1); EPI(c12, 1, 2); EPI(c13, 1, 3);
}

// ---------------- 5) sparse dilated attention (writes split-bf16 out) --------
__global__ void k_attn(const int* __restrict__ positions, int adim) {
    const float* gq = g_qkv;
    const float* gk = g_qkv + (size_t)NT*D_;
    const float* gv = g_qkv + (size_t)2*NT*D_;
    int n = blockIdx.x;
    int b = n / T_, t = n % T_;
    int h = threadIdx.x >> 5;
    int lane = threadIdx.x & 31;

    int cnt = 1 + min(t, 3);
    for (int kk = 4; kk <= t; kk <<= 1) cnt++;

    const float* qr = gq + (size_t)n*D_ + h*DH;
    float2 qv = *(const float2*)(qr + lane*2);

    int pos[AMAX];
    float sc[AMAX];
    #pragma unroll
    for (int a = 0; a < AMAX; a++) {
        if (a < cnt) {
            pos[a] = positions[t*adim + a];
            const float* kr = gk + (size_t)(b*T_ + pos[a])*D_ + h*DH;
            float2 kv = *(const float2*)(kr + lane*2);
            float s = qv.x*kv.x + qv.y*kv.y;
            #pragma unroll
            for (int off = 16; off; off >>= 1) s += __shfl_xor_sync(~0u, s, off);
            sc[a] = s * 0.125f;
        } else { pos[a] = 0; sc[a] = NEGF; }
    }
    float m = NEGF;
    #pragma unroll
    for (int a = 0; a < AMAX; a++) m = fmaxf(m, sc[a]);
    float sum = 0.f;
    #pragma unroll
    for (int a = 0; a < AMAX; a++) {
        sc[a] = (a < cnt) ? expf(sc[a] - m) : 0.f;
        sum += sc[a];
    }
    float inv = 1.f / sum;
    float2 acc = make_float2(0.f, 0.f);
    #pragma unroll
    for (int a = 0; a < AMAX; a++) {
        if (a < cnt) {
            const float* vr = gv + (size_t)(b*T_ + pos[a])*D_ + h*DH;
            float2 vv = *(const float2*)(vr + lane*2);
            float w = sc[a]*inv;
            acc.x += w*vv.x; acc.y += w*vv.y;
        }
    }
    size_t oidx = (size_t)n*D_ + h*DH + lane*2;
    split_bf(acc.x, g_Abh, g_Abl, oidx);
    split_bf(acc.y, g_Abh, g_Abl, oidx + 1);
}

// ---------------- launch ------------------------------------------------------
// Only harness pointers and plain ints cross the host->kernel boundary.
extern "C" void kernel_launch(void* const* d_in, const int* in_sizes, int n_in,
                              void* d_out, int out_size) {
    const float* x      = (const float*)d_in[0];
    const float* Wp     = (const float*)d_in[1];
    const float* Wi     = (const float*)d_in[2];
    const float* Wd     = (const float*)d_in[3];
    const float* gate_w = (const float*)d_in[4];
    const float* gate_b = (const float*)d_in[5];
    const float* kick_v = (const float*)d_in[6];
    const float* kick_w = (const float*)d_in[7];
    const float* kick_b = (const float*)d_in[8];
    const float* o_w    = (const float*)d_in[9];
    const int* positions = (const int*)d_in[10];
    int adim = in_sizes[10] / T_;

    cudaFuncSetAttribute(k_gemm, cudaFuncAttributeMaxDynamicSharedMemorySize, GEMM_SMEM);

    k_stats<<<NT, 256>>>(x, gate_w, gate_b, kick_w, kick_b);
    k_scan1<<<dim3(D_/256, CH, B_), 256>>>(x);
    k_scan2<<<dim3(D_/256, B_), 256>>>();

    k_buildA<<<NT, 256>>>(x, kick_v);              // all 3 projections
    k_buildB<<<3*D_, 256>>>(Wp, Wi, Wd);           // all 3 projections

    // q,k,v: one batched GEMM, gridDim.z = projection (M=4096, N=1024, K'=3072)
    k_gemm<<<dim3(D_/64, NT/128, 3), 256, GEMM_SMEM>>>(nullptr, 3*D_, 0);

    k_attn<<<NT, 512>>>(positions, adim);          // writes split-bf16 into g_Ab*
    k_split_ow<<<(D_*D_)/256, 256>>>(o_w, D_*D_);

    // out = attn @ o_w^T  (M=4096, N=1024, K=1024)
    k_gemm<<<dim3(D_/64, NT/128, 1), 256, GEMM_SMEM>>>((float*)d_out, D_, 1);
}